// round 3
// baseline (speedup 1.0000x reference)
#include <cuda_runtime.h>
#include <cuda_bf16.h>

// RMLoss: pairwise Bradley-Terry loss over 4096 variable-length segments.
//   pair_loss(i<j) = softplus(x_j - x_i) + BETA*0.5*(x_i^2 + x_j^2)
//   seg = mean over pairs; output = mean over segments.
// L2 term collapses: sum over pairs of 0.5(xi^2+xj^2) = 0.5*(L-1)*sum(x^2).

#define NSEG_MAX 4096
#define BETA 0.001f

__device__ float g_seg[NSEG_MAX];

__inline__ __device__ float warp_sum(float v) {
    #pragma unroll
    for (int o = 16; o; o >>= 1) v += __shfl_xor_sync(0xffffffffu, v, o);
    return v;
}

__global__ __launch_bounds__(128) void seg_kernel(
    const float* __restrict__ logits,
    const int*   __restrict__ cu32)   // int32 view of cu_lengths (int32 or int64)
{
    // Detect dtype layout: cu[0]==0 always; for int64 (little-endian) word[1]
    // is the high half of cu[0] == 0. For int32, word[1] = cu[1] >= 32.
    const int stride = (cu32[1] == 0) ? 2 : 1;

    const int s = blockIdx.x;
    const int a = cu32[s * stride];
    const int b = cu32[(s + 1) * stride];
    const int L = b - a;

    __shared__ float x[256];
    __shared__ float red[8];

    const int t = threadIdx.x;

    // Load segment into shared memory
    for (int k = t; k < L; k += blockDim.x) x[k] = logits[a + k];
    __syncthreads();

    float pacc = 0.0f;   // sum of softplus(x_j - x_i), i<j
    float sq   = 0.0f;   // sum of x^2

    for (int k = t; k < L; k += blockDim.x) {
        float v = x[k];
        sq += v * v;
    }

    // Row i = t: pairs (t, j) for j in (t, L)
    for (int i = t; i < L - 1; i += blockDim.x) {
        const float v = x[i];
        #pragma unroll 4
        for (int j = i + 1; j < L; ++j) {
            float d  = x[j] - v;           // neg - pos
            float ad = fabsf(d);
            // softplus(d) = max(d,0) + log(1 + exp(-|d|))
            float e  = __expf(-ad);
            pacc += fmaxf(d, 0.0f) + __logf(1.0f + e);
        }
    }

    // Block reduce (4 warps)
    pacc = warp_sum(pacc);
    sq   = warp_sum(sq);
    const int lane = t & 31, wid = t >> 5;
    if (lane == 0) { red[wid] = pacc; red[wid + 4] = sq; }
    __syncthreads();
    if (t == 0) {
        float ps = red[0] + red[1] + red[2] + red[3];
        float qs = red[4] + red[5] + red[6] + red[7];
        float nPairs = 0.5f * (float)L * (float)(L - 1);
        float total = ps + BETA * 0.5f * (float)(L - 1) * qs;
        g_seg[s] = total / nPairs;
    }
}

__global__ __launch_bounds__(1024) void reduce_kernel(float* __restrict__ out, int ns) {
    __shared__ float red[32];
    const int t = threadIdx.x;
    float acc = 0.0f;
    for (int i = t; i < ns; i += 1024) acc += g_seg[i];
    acc = warp_sum(acc);
    const int lane = t & 31, wid = t >> 5;
    if (lane == 0) red[wid] = acc;
    __syncthreads();
    if (wid == 0) {
        float v = (lane < 32) ? red[lane] : 0.0f;
        v = warp_sum(v);
        if (t == 0) out[0] = v / (float)ns;
    }
}

extern "C" void kernel_launch(void* const* d_in, const int* in_sizes, int n_in,
                              void* d_out, int out_size) {
    const float* logits = (const float*)d_in[0];
    const int*   cu32   = (const int*)d_in[1];

    // Number of segments: in_sizes[1] counts elements of cu_lengths (4097).
    // If the harness reported int64 as int32 words (8194), halve it.
    int ncu = in_sizes[1];
    int ns  = ncu - 1;
    if (ns > NSEG_MAX) ns = ncu / 2 - 1;
    if (ns > NSEG_MAX) ns = NSEG_MAX;

    seg_kernel<<<ns, 128>>>(logits, cu32);
    reduce_kernel<<<1, 1024>>>((float*)d_out, ns);
}